// round 17
// baseline (speedup 1.0000x reference)
#include <cuda_runtime.h>
#include <cuda_bf16.h>
#include <cstdint>
#include <cstddef>

#define DD      512
#define TSTEPS  256
#define BDIM    256
#define ZROWS   32768          // slices 0..127 kept as bf16 A-source

typedef unsigned short ushort_t;

// ---------------- static device storage (no allocs) ----------------
__device__ ushort_t g_zh[ZROWS * DD];        // z slices bf16 hi, [t][b][d]
__device__ ushort_t g_zl[ZROWS * DD];        // z slices bf16 lo
__device__ ushort_t g_z0h[BDIM * DD], g_z0l[BDIM * DD];
__device__ ushort_t g_pwh[8][DD * DD], g_pwl[8][DD * DD];    // K^(2^j) bf16
__device__ ushort_t g_pwth[8][DD * DD], g_pwtl[8][DD * DD];  // transposed [n][k]

// ---------------- helpers ----------------
__device__ __forceinline__ uint32_t smem_u32(const void* p) {
    uint32_t a;
    asm("{ .reg .u64 t; cvta.to.shared.u64 t, %1; cvt.u32.u64 %0, t; }"
        : "=r"(a) : "l"(p));
    return a;
}

#define CP16(dst, src) \
    asm volatile("cp.async.cg.shared.global [%0], [%1], 16;" \
                 :: "r"(dst), "l"(src) : "memory")
#define CP_COMMIT() asm volatile("cp.async.commit_group;" ::: "memory")
#define CP_WAIT0()  asm volatile("cp.async.wait_group 0;" ::: "memory")

#define LDSM4(R, a) \
    asm volatile("ldmatrix.sync.aligned.m8n8.x4.shared.b16 {%0,%1,%2,%3},[%4];" \
                 : "=r"((R)[0]), "=r"((R)[1]), "=r"((R)[2]), "=r"((R)[3]) : "r"(a))

#define MMA(C, A, b0v, b1v) \
    asm volatile("mma.sync.aligned.m16n8k16.row.col.f32.bf16.bf16.f32 " \
                 "{%0,%1,%2,%3},{%4,%5,%6,%7},{%8,%9},{%0,%1,%2,%3};" \
                 : "+f"((C)[0]), "+f"((C)[1]), "+f"((C)[2]), "+f"((C)[3]) \
                 : "r"((A)[0]), "r"((A)[1]), "r"((A)[2]), "r"((A)[3]), \
                   "r"(b0v), "r"(b1v))

__device__ __forceinline__ void split_bf16(float f, ushort_t& h, ushort_t& l) {
    __nv_bfloat16 bh = __float2bfloat16_rn(f);
    float fl = f - __bfloat162float(bh);
    __nv_bfloat16 bl = __float2bfloat16_rn(fl);
    h = *reinterpret_cast<ushort_t*>(&bh);
    l = *reinterpret_cast<ushort_t*>(&bl);
}

// ---------------- prep: K -> pw0 / pwT0 bf16 ; z0 -> z0 bf16 ----------------
__global__ void prep_kernel(const float* __restrict__ K, const float* __restrict__ z0)
{
    const int r = blockIdx.x;
    if (r < DD) {
        for (int c = threadIdx.x; c < DD; c += blockDim.x) {
            ushort_t h, l; split_bf16(K[r * DD + c], h, l);
            g_pwh[0][r * DD + c] = h;  g_pwl[0][r * DD + c] = l;
            g_pwth[0][c * DD + r] = h; g_pwtl[0][c * DD + r] = l;
        }
    } else {
        const int rr = r - DD;
        for (int c = threadIdx.x; c < DD; c += blockDim.x) {
            ushort_t h, l; split_bf16(z0[rr * DD + c], h, l);
            g_z0h[rr * DD + c] = h;  g_z0l[rr * DD + c] = l;
        }
    }
}

// ---------------- warp-MMA GEMM: D = A @ B^T, 3-term bf16 split -------------
// CTA tile TM x 128, 128 threads = 4 warps, warp grid (TM/32)m x (128/TM... )n:
//   TM=64: 2m x 2n, warp tile 32x64 (NT=8)  -- minimizes smem re-reads
//   TM=32: 1m x 4n, warp tile 32x32 (NT=4)  -- small-level latency config
// KC=64, 8 chunks, double buffer, ONE sync per chunk.
#define KC      64
#define CHUNKS  8

#define LOAD_CHUNK(chv, sv) do {                                               \
    const int kbase_ = (chv) * KC;                                             \
    /* A planes (hi, lo): TM rows x 64 bf16 each */                            \
    _Pragma("unroll")                                                          \
    for (int p_ = 0; p_ < 2; ++p_) {                                           \
        const ushort_t* sp_ = srcs[p_];                                        \
        _Pragma("unroll")                                                      \
        for (int rep_ = 0; rep_ < AREP; ++rep_) {                              \
            const int o_   = tid + rep_ * 128;                                 \
            const int row_ = o_ >> 3;                                          \
            const int cc_  = (o_ & 7) * 8;                                     \
            const uint32_t dst_ = sbu + (uint32_t)(sv) * STAGE                 \
                + (uint32_t)p_ * PLANE_A + (uint32_t)(row_ * 128)              \
                + (((uint32_t)(cc_ * 2)) ^ ((uint32_t)(row_ & 7) << 4));       \
            CP16(dst_, sp_ + (size_t)row_ * DD + kbase_ + cc_);                \
        }                                                                      \
    }                                                                          \
    /* B planes (hi, lo): 128 rows x 64 bf16 each */                           \
    _Pragma("unroll")                                                          \
    for (int p_ = 0; p_ < 2; ++p_) {                                           \
        const ushort_t* sp_ = srcs[2 + p_];                                    \
        _Pragma("unroll")                                                      \
        for (int rep_ = 0; rep_ < 8; ++rep_) {                                 \
            const int o_   = tid + rep_ * 128;                                 \
            const int row_ = o_ >> 3;                                          \
            const int cc_  = (o_ & 7) * 8;                                     \
            const uint32_t dst_ = sbu + (uint32_t)(sv) * STAGE                 \
                + 2 * PLANE_A + (uint32_t)p_ * PLANE_B + (uint32_t)(row_ * 128)\
                + (((uint32_t)(cc_ * 2)) ^ ((uint32_t)(row_ & 7) << 4));       \
            CP16(dst_, sp_ + (size_t)row_ * DD + kbase_ + cc_);                \
        }                                                                      \
    }                                                                          \
} while (0)

template <int TM>
__global__ void __launch_bounds__(128, 2)
gemm_tc(const ushort_t* __restrict__ a1h, const ushort_t* __restrict__ a1l,
        const ushort_t* __restrict__ a2h, const ushort_t* __restrict__ a2l,
        const ushort_t* __restrict__ bh,  const ushort_t* __restrict__ bl,
        float* __restrict__ outF,
        ushort_t* __restrict__ zH, ushort_t* __restrict__ zL,
        ushort_t* __restrict__ nxtH, ushort_t* __restrict__ nxtL,
        ushort_t* __restrict__ nxtTH, ushort_t* __restrict__ nxtTL,
        int M1, int tofs, int dstOfs)
{
    constexpr int MWARPS  = TM / 32;           // warps along M (2 or 1)
    constexpr int NWN     = 4 / MWARPS;        // warps along N (2 or 4)
    constexpr int WNT     = 128 / NWN;         // warp N width (64 or 32)
    constexpr int NB      = WNT / 16;          // B ldmatrix groups (4 or 2)
    constexpr int NT      = WNT / 8;           // n-tiles per warp (8 or 4)
    constexpr int AREP    = TM / 16;           // A loader reps per plane (4 or 2)
    constexpr int PLANE_A = TM * 128;
    constexpr int PLANE_B = 16384;
    constexpr int STAGE   = 2 * PLANE_A + 2 * PLANE_B;

    extern __shared__ char dsm[];
    char* sb = (char*)(((uintptr_t)dsm + 1023) & ~(uintptr_t)1023);
    const uint32_t sbu = smem_u32(sb);

    const int tid  = threadIdx.x;
    const int wid  = tid >> 5;
    const int lane = tid & 31;
    const int wm   = wid & (MWARPS - 1);       // warp row (32 rows)
    const int wn   = wid / MWARPS;             // warp col (WNT cols)
    const int rowBlk = blockIdx.x * TM;
    const int n0     = blockIdx.y * 128;

    // source row bases (CTA uniform: M1 % TM == 0)
    const bool inA1 = (rowBlk < M1);
    const ushort_t* srcs[4];
    const size_t aOfs = (size_t)(inA1 ? rowBlk : (rowBlk - M1)) * DD;
    srcs[0] = (inA1 ? a1h : a2h) + aOfs;
    srcs[1] = (inA1 ? a1l : a2l) + aOfs;
    srcs[2] = bh + (size_t)n0 * DD;
    srcs[3] = bl + (size_t)n0 * DD;

    // ldmatrix per-lane address precompute (SW128: col ^ ((row&7)<<4))
    uint32_t aOff[2], aXor[2];
    {
        const int r0 = wm * 32 + (lane & 15);
        #pragma unroll
        for (int mt = 0; mt < 2; ++mt) {
            const int r = r0 + mt * 16;
            aOff[mt] = (uint32_t)(r * 128);
            aXor[mt] = (uint32_t)((r & 7) << 4);
        }
    }
    const uint32_t aColB = (uint32_t)((lane >> 4) * 16);
    uint32_t bOff[NB], bXor[NB];
    {
        const int r0 = wn * WNT + (lane & 7) + 8 * (lane >> 4);
        #pragma unroll
        for (int np = 0; np < NB; ++np) {
            const int r = r0 + np * 16;
            bOff[np] = (uint32_t)(r * 128);
            bXor[np] = (uint32_t)((r & 7) << 4);
        }
    }
    const uint32_t bColB = (uint32_t)(((lane >> 3) & 1) * 16);

    float acc[2][NT][4];
    #pragma unroll
    for (int mt = 0; mt < 2; ++mt)
        #pragma unroll
        for (int nt = 0; nt < NT; ++nt)
            #pragma unroll
            for (int q = 0; q < 4; ++q) acc[mt][nt][q] = 0.f;

    LOAD_CHUNK(0, 0); CP_COMMIT();

    for (int ch = 0; ch < CHUNKS; ++ch) {
        CP_WAIT0();              // chunk ch arrived (sole outstanding group)
        __syncthreads();         // data visible; every warp finished compute(ch-1)
        if (ch + 1 < CHUNKS) { LOAD_CHUNK(ch + 1, (ch + 1) & 1); CP_COMMIT(); }

        const uint32_t base = sbu + (uint32_t)(ch & 1) * STAGE;
        #pragma unroll
        for (int k16 = 0; k16 < 4; ++k16) {
            const uint32_t cA = (uint32_t)(k16 * 32) + aColB;
            const uint32_t cB = (uint32_t)(k16 * 32) + bColB;
            uint32_t ah[2][4], al[2][4], bhf[NB][4], blf[NB][4];
            #pragma unroll
            for (int mt = 0; mt < 2; ++mt) {
                LDSM4(ah[mt], base + 0 * PLANE_A + aOff[mt] + (cA ^ aXor[mt]));
                LDSM4(al[mt], base + 1 * PLANE_A + aOff[mt] + (cA ^ aXor[mt]));
            }
            #pragma unroll
            for (int np = 0; np < NB; ++np) {
                LDSM4(bhf[np], base + 2 * PLANE_A + 0 * PLANE_B + bOff[np] + (cB ^ bXor[np]));
                LDSM4(blf[np], base + 2 * PLANE_A + 1 * PLANE_B + bOff[np] + (cB ^ bXor[np]));
            }
            // term-major; per-acc order (hh, hl, lh) unchanged -> bitwise identical
            #pragma unroll
            for (int mt = 0; mt < 2; ++mt)        // hi * hi
                #pragma unroll
                for (int nt = 0; nt < NT; ++nt) {
                    const uint32_t* bp = &bhf[nt >> 1][(nt & 1) * 2];
                    MMA(acc[mt][nt], ah[mt], bp[0], bp[1]);
                }
            #pragma unroll
            for (int mt = 0; mt < 2; ++mt)        // hi * lo
                #pragma unroll
                for (int nt = 0; nt < NT; ++nt) {
                    const uint32_t* lp = &blf[nt >> 1][(nt & 1) * 2];
                    MMA(acc[mt][nt], ah[mt], lp[0], lp[1]);
                }
            #pragma unroll
            for (int mt = 0; mt < 2; ++mt)        // lo * hi
                #pragma unroll
                for (int nt = 0; nt < NT; ++nt) {
                    const uint32_t* bp = &bhf[nt >> 1][(nt & 1) * 2];
                    MMA(acc[mt][nt], al[mt], bp[0], bp[1]);
                }
        }
    }

    // epilogue: D row = lane>>2 (+8), col = 2*(lane&3)
    #pragma unroll
    for (int mt = 0; mt < 2; ++mt)
        #pragma unroll
        for (int nt = 0; nt < NT; ++nt) {
            const int rbase = rowBlk + wm * 32 + mt * 16 + (lane >> 2);
            const int col   = n0 + wn * WNT + nt * 8 + 2 * (lane & 3);
            #pragma unroll
            for (int half = 0; half < 2; ++half) {
                const int g = rbase + half * 8;
                const float c0 = acc[mt][nt][half * 2];
                const float c1 = acc[mt][nt][half * 2 + 1];
                ushort_t h0, l0, h1, l1;
                split_bf16(c0, h0, l0); split_bf16(c1, h1, l1);
                const uint32_t ph = (uint32_t)h0 | ((uint32_t)h1 << 16);
                const uint32_t pl = (uint32_t)l0 | ((uint32_t)l1 << 16);
                if (inA1) {
                    float2 v; v.x = c0; v.y = c1;
                    *reinterpret_cast<float2*>(
                        outF + ((size_t)(g & 255) * TSTEPS + (size_t)tofs + (g >> 8)) * DD
                             + col) = v;
                    const int zr = g + dstOfs;
                    if (zr < ZROWS) {
                        *reinterpret_cast<uint32_t*>(zH + (size_t)zr * DD + col) = ph;
                        *reinterpret_cast<uint32_t*>(zL + (size_t)zr * DD + col) = pl;
                    }
                } else {
                    const int r = g - M1;
                    const size_t o = (size_t)r * DD + col;
                    *reinterpret_cast<uint32_t*>(nxtH + o) = ph;
                    *reinterpret_cast<uint32_t*>(nxtL + o) = pl;
                    // fused transpose: [n][k] planes for next level's B operand
                    nxtTH[(size_t)col * DD + r]       = h0;
                    nxtTH[(size_t)(col + 1) * DD + r] = h1;
                    nxtTL[(size_t)col * DD + r]       = l0;
                    nxtTL[(size_t)(col + 1) * DD + r] = l1;
                }
            }
        }
}

// ---------------- host ----------------
extern "C" void kernel_launch(void* const* d_in, const int* in_sizes, int n_in,
                              void* d_out, int out_size)
{
    const float* z0 = (const float*)d_in[0];
    const float* K  = (const float*)d_in[1];
    float* out = (float*)d_out;

    ushort_t *zh, *zl, *z0h, *z0l, *pwh, *pwl, *pwth, *pwtl;
    cudaGetSymbolAddress((void**)&zh,   g_zh);
    cudaGetSymbolAddress((void**)&zl,   g_zl);
    cudaGetSymbolAddress((void**)&z0h,  g_z0h);
    cudaGetSymbolAddress((void**)&z0l,  g_z0l);
    cudaGetSymbolAddress((void**)&pwh,  g_pwh);
    cudaGetSymbolAddress((void**)&pwl,  g_pwl);
    cudaGetSymbolAddress((void**)&pwth, g_pwth);
    cudaGetSymbolAddress((void**)&pwtl, g_pwtl);

    const int SMEM64 = 2 * (2 * 64 * 128 + 32768) + 1024;   // 99328 -> 2 CTAs/SM
    const int SMEM32 = 2 * (2 * 32 * 128 + 32768) + 1024;   // 82944
    cudaFuncSetAttribute(gemm_tc<64>, cudaFuncAttributeMaxDynamicSharedMemorySize, SMEM64);
    cudaFuncSetAttribute(gemm_tc<32>, cudaFuncAttributeMaxDynamicSharedMemorySize, SMEM32);

    prep_kernel<<<DD + BDIM, 256>>>(K, z0);

    auto launch = [&](const ushort_t* A1h, const ushort_t* A1l,
                      const ushort_t* A2h, const ushort_t* A2l,
                      const ushort_t* Bh,  const ushort_t* Bl,
                      ushort_t* nH, ushort_t* nL, ushort_t* nTH, ushort_t* nTL,
                      int rows, int M1, int tofs, int dstOfs) {
        if ((rows / 64) * 4 < 148) {
            gemm_tc<32><<<dim3(rows / 32, 4), 128, SMEM32>>>(
                A1h, A1l, A2h, A2l, Bh, Bl, out, zh, zl,
                nH, nL, nTH, nTL, M1, tofs, dstOfs);
        } else {
            gemm_tc<64><<<dim3(rows / 64, 4), 128, SMEM64>>>(
                A1h, A1l, A2h, A2l, Bh, Bl, out, zh, zl,
                nH, nL, nTH, nTL, M1, tofs, dstOfs);
        }
    };

    // G0: slice 0 = z0 @ K  (no squaring rows; nxt args unused)
    launch(z0h, z0l, z0h, z0l, pwth, pwtl,
           pwh, pwl, pwth, pwtl, BDIM, BDIM, 0, 0);

    // Level j: [slices 0..n-1] @ K^n -> slices n..2n-1 ; append K^n@K^n -> K^(2n)
    for (int j = 0; j < 8; ++j) {
        const int n  = 1 << j;
        const int M1 = BDIM * n;
        const int rows = M1 + ((j < 7) ? DD : 0);
        const size_t mo = (size_t)j * DD * DD;
        const size_t no = (size_t)(j < 7 ? j + 1 : 0) * DD * DD;
        launch(zh, zl, pwh + mo, pwl + mo, pwth + mo, pwtl + mo,
               pwh + no, pwl + no, pwth + no, pwtl + no,
               rows, M1, n, M1);
    }
}